// round 14
// baseline (speedup 1.0000x reference)
#include <cuda_runtime.h>
#include <cuda_bf16.h>
#include <math.h>

// Problem constants (match reference)
#define N_NODES 50000
#define E_EDGES 800000
#define K_IN    256
#define M_OUT   128   // H*D = 4*32
#define H_HEADS 4
#define D_HEAD  32
#define NEG_SLOPE 0.2f

#define SCAN_CHUNK 4096
#define SCAN_BLOCKS ((N_NODES + SCAN_CHUNK - 1) / SCAN_CHUNK)   // 13

typedef unsigned long long ull;

// ---------------- scratch (device globals; no allocation allowed) ----------
__device__ float g_ft[(size_t)N_NODES * M_OUT];   // projected features [N,128]
__device__ float g_el[N_NODES * H_HEADS];         // per-node left logits
__device__ float g_er[N_NODES * H_HEADS];         // per-node right logits
__device__ int   g_deg[N_NODES];
__device__ int   g_pos[N_NODES];                  // running fill cursor (init = offsets)
__device__ int   g_off[N_NODES + 1];
__device__ int   g_csr_src[E_EDGES];
__device__ int   g_bsum[SCAN_BLOCKS];             // per-chunk sums for 2-phase scan

// ---------------- f32x2 packed-FMA helpers (sm_100+) ----------------------
__device__ __forceinline__ ull pack2(float x, float y) {
    ull r;
    asm("mov.b64 %0, {%1,%2};" : "=l"(r) : "f"(x), "f"(y));
    return r;
}
__device__ __forceinline__ void unpack2(ull v, float& x, float& y) {
    asm("mov.b64 {%0,%1}, %2;" : "=f"(x), "=f"(y) : "l"(v));
}
__device__ __forceinline__ void ffma2(ull& d, ull a, ull b) {
    asm("fma.rn.f32x2 %0, %1, %2, %0;" : "+l"(d) : "l"(a), "l"(b));
}

// ---------------- kernel 0: zero degree counters (int4) --------------------
__global__ void zero_kernel() {
    int i = blockIdx.x * blockDim.x + threadIdx.x;   // 12500 int4
    if (i * 4 < N_NODES)
        *reinterpret_cast<int4*>(&g_deg[i * 4]) = make_int4(0, 0, 0, 0);
}

// ---------------- kernel 1: GEMM ft = feat @ W + fused el/er ---------------
// 64 rows x 128 cols per block, 256 threads.
// warp ty owns rows ty*8..ty*8+7; lane tx owns cols tx*4..tx*4+3.
// A tile stored in smem as duplicated (a,a) f32x2 pairs -> broadcast LDS.128.
// B tile read directly as native f32x2 pairs (adjacent cols) -> no packing.
#define BR 64
#define KC 32
#define BS_LD 132

__global__ __launch_bounds__(256) void gemm_kernel(const float* __restrict__ A,
                                                   const float* __restrict__ B,
                                                   const float* __restrict__ attn_l,
                                                   const float* __restrict__ attn_r) {
    __shared__ ull   As2[KC][BR];      // 16 KB, [k][row] duplicated pairs
    __shared__ float Bs[KC][BS_LD];    // ~16.9 KB

    const int tid  = threadIdx.x;
    const int row0 = blockIdx.x * BR;
    const int ty   = tid >> 5;   // 0..7
    const int tx   = tid & 31;   // 0..31

    // attn slices for fused epilogue
    const float4 al = *reinterpret_cast<const float4*>(&attn_l[tx * 4]);
    const float4 ar = *reinterpret_cast<const float4*>(&attn_r[tx * 4]);

    ull acc[8][2];
#pragma unroll
    for (int i = 0; i < 8; i++) { acc[i][0] = 0ULL; acc[i][1] = 0ULL; }

    // A fill: row = tid>>2 (0..63), k offsets (tid&3)*8 .. +7  (8 floats/thread)
    const int a_r = tid >> 2;
    const int a_k = (tid & 3) * 8;
    // B fill: k row = tid>>3 (0..31), col base (tid&7)*16 (16 floats/thread)
    const int b_k = tid >> 3;
    const int b_c = (tid & 7) * 16;

    for (int k0 = 0; k0 < K_IN; k0 += KC) {
        {
            int gr = row0 + a_r;
            float4 v0 = make_float4(0.f, 0.f, 0.f, 0.f), v1 = v0;
            if (gr < N_NODES) {
                const float* ap = &A[(size_t)gr * K_IN + k0 + a_k];
                v0 = *reinterpret_cast<const float4*>(ap);
                v1 = *reinterpret_cast<const float4*>(ap + 4);
            }
            As2[a_k + 0][a_r] = pack2(v0.x, v0.x);
            As2[a_k + 1][a_r] = pack2(v0.y, v0.y);
            As2[a_k + 2][a_r] = pack2(v0.z, v0.z);
            As2[a_k + 3][a_r] = pack2(v0.w, v0.w);
            As2[a_k + 4][a_r] = pack2(v1.x, v1.x);
            As2[a_k + 5][a_r] = pack2(v1.y, v1.y);
            As2[a_k + 6][a_r] = pack2(v1.z, v1.z);
            As2[a_k + 7][a_r] = pack2(v1.w, v1.w);
        }
        {
            const float* bp = &B[(size_t)(k0 + b_k) * M_OUT + b_c];
#pragma unroll
            for (int q = 0; q < 4; q++)
                *reinterpret_cast<float4*>(&Bs[b_k][b_c + q * 4]) =
                    *reinterpret_cast<const float4*>(bp + q * 4);
        }
        __syncthreads();

#pragma unroll
        for (int k = 0; k < KC; k++) {
            // 2 b-pairs (4 cols), no packing needed
            ulonglong2 bb = *reinterpret_cast<const ulonglong2*>(&Bs[k][tx * 4]);
            // 8 a-pairs (8 rows) via 4 broadcast LDS.128
            const ulonglong2* arow =
                reinterpret_cast<const ulonglong2*>(&As2[k][ty * 8]);
            ulonglong2 a01 = arow[0];
            ulonglong2 a23 = arow[1];
            ulonglong2 a45 = arow[2];
            ulonglong2 a67 = arow[3];
            ffma2(acc[0][0], a01.x, bb.x); ffma2(acc[0][1], a01.x, bb.y);
            ffma2(acc[1][0], a01.y, bb.x); ffma2(acc[1][1], a01.y, bb.y);
            ffma2(acc[2][0], a23.x, bb.x); ffma2(acc[2][1], a23.x, bb.y);
            ffma2(acc[3][0], a23.y, bb.x); ffma2(acc[3][1], a23.y, bb.y);
            ffma2(acc[4][0], a45.x, bb.x); ffma2(acc[4][1], a45.x, bb.y);
            ffma2(acc[5][0], a45.y, bb.x); ffma2(acc[5][1], a45.y, bb.y);
            ffma2(acc[6][0], a67.x, bb.x); ffma2(acc[6][1], a67.x, bb.y);
            ffma2(acc[7][0], a67.y, bb.x); ffma2(acc[7][1], a67.y, bb.y);
        }
        __syncthreads();
    }

    // epilogue: store ft rows + fused el/er (dot with attn over 8-lane head groups)
#pragma unroll
    for (int i = 0; i < 8; i++) {
        int gr = row0 + ty * 8 + i;
        if (gr < N_NODES) {
            float4 o;
            unpack2(acc[i][0], o.x, o.y);
            unpack2(acc[i][1], o.z, o.w);
            *reinterpret_cast<float4*>(&g_ft[(size_t)gr * M_OUT + tx * 4]) = o;

            float pl = o.x * al.x + o.y * al.y + o.z * al.z + o.w * al.w;
            float pr = o.x * ar.x + o.y * ar.y + o.z * ar.z + o.w * ar.w;
#pragma unroll
            for (int off = 1; off < 8; off <<= 1) {
                pl += __shfl_xor_sync(0xFFFFFFFFu, pl, off);
                pr += __shfl_xor_sync(0xFFFFFFFFu, pr, off);
            }
            if ((tx & 7) == 0) {
                g_el[gr * H_HEADS + (tx >> 3)] = pl;
                g_er[gr * H_HEADS + (tx >> 3)] = pr;
            }
        }
    }
}

// ---------------- kernel 2: in-degree histogram (4 edges/thread) -----------
__global__ void hist_kernel(const int* __restrict__ dst) {
    int i = blockIdx.x * blockDim.x + threadIdx.x;   // 200000 threads
    if (i * 4 < E_EDGES) {
        int4 d4 = *reinterpret_cast<const int4*>(&dst[i * 4]);
        atomicAdd(&g_deg[d4.x], 1);
        atomicAdd(&g_deg[d4.y], 1);
        atomicAdd(&g_deg[d4.z], 1);
        atomicAdd(&g_deg[d4.w], 1);
    }
}

// ---------------- kernel 3a: per-chunk degree sums (phase 1 of scan) -------
__global__ __launch_bounds__(1024) void scan_reduce_kernel() {
    __shared__ int warp_sums[32];
    const int tid  = threadIdx.x;
    const int lane = tid & 31;
    const int w    = tid >> 5;
    const int i4   = blockIdx.x * SCAN_CHUNK + tid * 4;

    int4 v = make_int4(0, 0, 0, 0);
    if (i4 < N_NODES)   // N_NODES % 4 == 0 -> whole-int4 guard is exact
        v = *reinterpret_cast<const int4*>(&g_deg[i4]);
    int s = v.x + v.y + v.z + v.w;
#pragma unroll
    for (int o = 16; o > 0; o >>= 1) s += __shfl_xor_sync(0xFFFFFFFFu, s, o);
    if (lane == 0) warp_sums[w] = s;
    __syncthreads();
    if (w == 0) {
        int t = warp_sums[lane];
#pragma unroll
        for (int o = 16; o > 0; o >>= 1) t += __shfl_xor_sync(0xFFFFFFFFu, t, o);
        if (lane == 0) g_bsum[blockIdx.x] = t;
    }
}

// ---------------- kernel 3b: per-chunk exclusive scan (phase 2) ------------
__global__ __launch_bounds__(1024) void scan_blocks_kernel() {
    __shared__ int warp_sums[32];
    __shared__ int s_base;
    const int tid  = threadIdx.x;
    const int lane = tid & 31;
    const int w    = tid >> 5;
    const int blk  = blockIdx.x;

    // block base = exclusive prefix of g_bsum over preceding chunks
    if (w == 0) {
        int v = (lane < blk) ? g_bsum[lane] : 0;   // SCAN_BLOCKS=13 <= 32
#pragma unroll
        for (int o = 16; o > 0; o >>= 1) v += __shfl_xor_sync(0xFFFFFFFFu, v, o);
        if (lane == 0) s_base = v;
    }
    if (tid == 0 && blk == 0) g_off[0] = 0;
    __syncthreads();

    const int i4 = blk * SCAN_CHUNK + tid * 4;
    int4 v = make_int4(0, 0, 0, 0);
    if (i4 < N_NODES)
        v = *reinterpret_cast<const int4*>(&g_deg[i4]);
    int tsum = v.x + v.y + v.z + v.w;

    int x = tsum;
#pragma unroll
    for (int o = 1; o < 32; o <<= 1) {
        int y = __shfl_up_sync(0xFFFFFFFFu, x, o);
        if (lane >= o) x += y;
    }
    if (lane == 31) warp_sums[w] = x;
    __syncthreads();
    if (w == 0) {
        int y = warp_sums[lane];
#pragma unroll
        for (int o = 1; o < 32; o <<= 1) {
            int z = __shfl_up_sync(0xFFFFFFFFu, y, o);
            if (lane >= o) y += z;
        }
        warp_sums[lane] = y;
    }
    __syncthreads();

    int excl = (x - tsum) + (w > 0 ? warp_sums[w - 1] : 0) + s_base;
    if (i4 < N_NODES) {
        int p1 = excl + v.x;
        int p2 = p1 + v.y;
        int p3 = p2 + v.z;
        int p4 = p3 + v.w;
        *reinterpret_cast<int4*>(&g_pos[i4]) = make_int4(excl, p1, p2, p3);
        g_off[i4 + 1] = p1;
        g_off[i4 + 2] = p2;
        g_off[i4 + 3] = p3;
        g_off[i4 + 4] = p4;
    }
}

// ---------------- kernel 4: scatter edges into CSR-by-dst (x4) -------------
__global__ void scatter_kernel(const int* __restrict__ src,
                               const int* __restrict__ dst) {
    int i = blockIdx.x * blockDim.x + threadIdx.x;
    if (i * 4 < E_EDGES) {
        int4 d4 = *reinterpret_cast<const int4*>(&dst[i * 4]);
        int4 s4 = *reinterpret_cast<const int4*>(&src[i * 4]);
        g_csr_src[atomicAdd(&g_pos[d4.x], 1)] = s4.x;
        g_csr_src[atomicAdd(&g_pos[d4.y], 1)] = s4.y;
        g_csr_src[atomicAdd(&g_pos[d4.z], 1)] = s4.z;
        g_csr_src[atomicAdd(&g_pos[d4.w], 1)] = s4.w;
    }
}

// ---------------- kernel 5: fused softmax + aggregation, 1 warp / dst ------
// Softmax shift dropped: scores are leaky_relu of small dot sums (|x| << 80),
// exp cannot overflow, and softmax is shift-invariant.
// Software-pipelined: next edge's csr index + el logit prefetched one
// iteration ahead so their L2 latency overlaps the current ft gather.
__global__ __launch_bounds__(256) void agg_kernel(const float* __restrict__ bias,
                                                  float* __restrict__ out) {
    int d    = (blockIdx.x * blockDim.x + threadIdx.x) >> 5;
    int lane = threadIdx.x & 31;
    if (d >= N_NODES) return;

    int start = g_off[d];
    int end   = g_off[d + 1];

    int   h  = lane >> 3;                 // head owning lanes' 4 output dims
    float er = g_er[d * H_HEADS + h];

    float4 acc  = make_float4(0.f, 0.f, 0.f, 0.f);
    float  ssum = 0.f;

    int   s_nx  = 0;
    float el_nx = 0.f;
    if (start < end) {
        s_nx  = g_csr_src[start];
        el_nx = g_el[s_nx * H_HEADS + h];
    }
    for (int j = start; j < end; ++j) {
        int   s   = s_nx;
        float elv = el_nx;
        int   jn  = j + 1;
        if (jn < end) {
            s_nx  = g_csr_src[jn];
            el_nx = g_el[s_nx * H_HEADS + h];
        }
        float4 f = *reinterpret_cast<const float4*>(
            &g_ft[(size_t)s * M_OUT + lane * 4]);
        float x = elv + er;
        x = (x > 0.f) ? x : NEG_SLOPE * x;
        float a = __expf(x);              // same across the 8 lanes of a head
        ssum += a;
        acc.x += f.x * a; acc.y += f.y * a; acc.z += f.z * a; acc.w += f.w * a;
    }
    float inv = (end > start) ? 1.f / ssum : 0.f;

    float4 b = *reinterpret_cast<const float4*>(&bias[lane * 4]);
    float4 o;
    o.x = acc.x * inv + b.x;
    o.y = acc.y * inv + b.y;
    o.z = acc.z * inv + b.z;
    o.w = acc.w * inv + b.w;
    *reinterpret_cast<float4*>(&out[(size_t)d * M_OUT + lane * 4]) = o;
}

// ---------------- launch ----------------------------------------------------
extern "C" void kernel_launch(void* const* d_in, const int* in_sizes, int n_in,
                              void* d_out, int out_size) {
    const float* feat   = (const float*)d_in[0];
    const int*   src    = (const int*)d_in[1];
    const int*   dst    = (const int*)d_in[2];
    const float* W      = (const float*)d_in[3];
    const float* attn_l = (const float*)d_in[4];
    const float* attn_r = (const float*)d_in[5];
    const float* bias   = (const float*)d_in[6];
    float* out = (float*)d_out;

    zero_kernel<<<(N_NODES / 4 + 255) / 256, 256>>>();
    gemm_kernel<<<(N_NODES + BR - 1) / BR, 256>>>(feat, W, attn_l, attn_r);
    hist_kernel<<<(E_EDGES / 4 + 255) / 256, 256>>>(dst);
    scan_reduce_kernel<<<SCAN_BLOCKS, 1024>>>();
    scan_blocks_kernel<<<SCAN_BLOCKS, 1024>>>();
    scatter_kernel<<<(E_EDGES / 4 + 255) / 256, 256>>>(src, dst);
    agg_kernel<<<(N_NODES + 7) / 8, 256>>>(bias, out);
}

// round 15
// speedup vs baseline: 1.0011x; 1.0011x over previous
#include <cuda_runtime.h>
#include <cuda_bf16.h>
#include <math.h>

// Problem constants (match reference)
#define N_NODES 50000
#define E_EDGES 800000
#define K_IN    256
#define M_OUT   128   // H*D = 4*32
#define H_HEADS 4
#define D_HEAD  32
#define NEG_SLOPE 0.2f

#define SCAN_CHUNK 4096
#define SCAN_BLOCKS ((N_NODES + SCAN_CHUNK - 1) / SCAN_CHUNK)   // 13

typedef unsigned long long ull;

// ---------------- scratch (device globals; no allocation allowed) ----------
__device__ float g_ft[(size_t)N_NODES * M_OUT];   // projected features [N,128]
__device__ float g_el[N_NODES * H_HEADS];         // per-node left logits
__device__ float g_er[N_NODES * H_HEADS];         // per-node right logits
__device__ int   g_deg[N_NODES];
__device__ int   g_pos[N_NODES];                  // running fill cursor (init = offsets)
__device__ int   g_off[N_NODES + 1];
__device__ int   g_csr_src[E_EDGES];
__device__ int   g_bsum[SCAN_BLOCKS];             // per-chunk sums for 2-phase scan

// ---------------- f32x2 packed-FMA helpers (sm_100+) ----------------------
__device__ __forceinline__ ull pack2(float x, float y) {
    ull r;
    asm("mov.b64 %0, {%1,%2};" : "=l"(r) : "f"(x), "f"(y));
    return r;
}
__device__ __forceinline__ void unpack2(ull v, float& x, float& y) {
    asm("mov.b64 {%0,%1}, %2;" : "=f"(x), "=f"(y) : "l"(v));
}
__device__ __forceinline__ void ffma2(ull& d, ull a, ull b) {
    asm("fma.rn.f32x2 %0, %1, %2, %0;" : "+l"(d) : "l"(a), "l"(b));
}

// ---------------- kernel 0: zero degree counters (int4) --------------------
__global__ void zero_kernel() {
    int i = blockIdx.x * blockDim.x + threadIdx.x;   // 12500 int4
    if (i * 4 < N_NODES)
        *reinterpret_cast<int4*>(&g_deg[i * 4]) = make_int4(0, 0, 0, 0);
}

// ---------------- kernel 1: GEMM ft = feat @ W + fused el/er ---------------
// 64 rows x 128 cols per block, 256 threads.
// warp ty owns rows ty*8..ty*8+7; lane tx owns cols tx*4..tx*4+3.
// A tile stored in smem as duplicated (a,a) f32x2 pairs -> broadcast LDS.128.
// B tile read directly as native f32x2 pairs (adjacent cols) -> no packing.
#define BR 64
#define KC 32
#define BS_LD 132

__global__ __launch_bounds__(256) void gemm_kernel(const float* __restrict__ A,
                                                   const float* __restrict__ B,
                                                   const float* __restrict__ attn_l,
                                                   const float* __restrict__ attn_r) {
    __shared__ ull   As2[KC][BR];      // 16 KB, [k][row] duplicated pairs
    __shared__ float Bs[KC][BS_LD];    // ~16.9 KB

    const int tid  = threadIdx.x;
    const int row0 = blockIdx.x * BR;
    const int ty   = tid >> 5;   // 0..7
    const int tx   = tid & 31;   // 0..31

    // attn slices for fused epilogue
    const float4 al = *reinterpret_cast<const float4*>(&attn_l[tx * 4]);
    const float4 ar = *reinterpret_cast<const float4*>(&attn_r[tx * 4]);

    ull acc[8][2];
#pragma unroll
    for (int i = 0; i < 8; i++) { acc[i][0] = 0ULL; acc[i][1] = 0ULL; }

    // A fill: row = tid>>2 (0..63), k offsets (tid&3)*8 .. +7  (8 floats/thread)
    const int a_r = tid >> 2;
    const int a_k = (tid & 3) * 8;
    // B fill: k row = tid>>3 (0..31), col base (tid&7)*16 (16 floats/thread)
    const int b_k = tid >> 3;
    const int b_c = (tid & 7) * 16;

    for (int k0 = 0; k0 < K_IN; k0 += KC) {
        {
            int gr = row0 + a_r;
            float4 v0 = make_float4(0.f, 0.f, 0.f, 0.f), v1 = v0;
            if (gr < N_NODES) {
                const float* ap = &A[(size_t)gr * K_IN + k0 + a_k];
                v0 = *reinterpret_cast<const float4*>(ap);
                v1 = *reinterpret_cast<const float4*>(ap + 4);
            }
            As2[a_k + 0][a_r] = pack2(v0.x, v0.x);
            As2[a_k + 1][a_r] = pack2(v0.y, v0.y);
            As2[a_k + 2][a_r] = pack2(v0.z, v0.z);
            As2[a_k + 3][a_r] = pack2(v0.w, v0.w);
            As2[a_k + 4][a_r] = pack2(v1.x, v1.x);
            As2[a_k + 5][a_r] = pack2(v1.y, v1.y);
            As2[a_k + 6][a_r] = pack2(v1.z, v1.z);
            As2[a_k + 7][a_r] = pack2(v1.w, v1.w);
        }
        {
            const float* bp = &B[(size_t)(k0 + b_k) * M_OUT + b_c];
#pragma unroll
            for (int q = 0; q < 4; q++)
                *reinterpret_cast<float4*>(&Bs[b_k][b_c + q * 4]) =
                    *reinterpret_cast<const float4*>(bp + q * 4);
        }
        __syncthreads();

#pragma unroll
        for (int k = 0; k < KC; k++) {
            // 2 b-pairs (4 cols), no packing needed
            ulonglong2 bb = *reinterpret_cast<const ulonglong2*>(&Bs[k][tx * 4]);
            // 8 a-pairs (8 rows) via 4 broadcast LDS.128
            const ulonglong2* arow =
                reinterpret_cast<const ulonglong2*>(&As2[k][ty * 8]);
            ulonglong2 a01 = arow[0];
            ulonglong2 a23 = arow[1];
            ulonglong2 a45 = arow[2];
            ulonglong2 a67 = arow[3];
            ffma2(acc[0][0], a01.x, bb.x); ffma2(acc[0][1], a01.x, bb.y);
            ffma2(acc[1][0], a01.y, bb.x); ffma2(acc[1][1], a01.y, bb.y);
            ffma2(acc[2][0], a23.x, bb.x); ffma2(acc[2][1], a23.x, bb.y);
            ffma2(acc[3][0], a23.y, bb.x); ffma2(acc[3][1], a23.y, bb.y);
            ffma2(acc[4][0], a45.x, bb.x); ffma2(acc[4][1], a45.x, bb.y);
            ffma2(acc[5][0], a45.y, bb.x); ffma2(acc[5][1], a45.y, bb.y);
            ffma2(acc[6][0], a67.x, bb.x); ffma2(acc[6][1], a67.x, bb.y);
            ffma2(acc[7][0], a67.y, bb.x); ffma2(acc[7][1], a67.y, bb.y);
        }
        __syncthreads();
    }

    // epilogue: store ft rows + fused el/er (dot with attn over 8-lane head groups)
#pragma unroll
    for (int i = 0; i < 8; i++) {
        int gr = row0 + ty * 8 + i;
        if (gr < N_NODES) {
            float4 o;
            unpack2(acc[i][0], o.x, o.y);
            unpack2(acc[i][1], o.z, o.w);
            *reinterpret_cast<float4*>(&g_ft[(size_t)gr * M_OUT + tx * 4]) = o;

            float pl = o.x * al.x + o.y * al.y + o.z * al.z + o.w * al.w;
            float pr = o.x * ar.x + o.y * ar.y + o.z * ar.z + o.w * ar.w;
#pragma unroll
            for (int off = 1; off < 8; off <<= 1) {
                pl += __shfl_xor_sync(0xFFFFFFFFu, pl, off);
                pr += __shfl_xor_sync(0xFFFFFFFFu, pr, off);
            }
            if ((tx & 7) == 0) {
                g_el[gr * H_HEADS + (tx >> 3)] = pl;
                g_er[gr * H_HEADS + (tx >> 3)] = pr;
            }
        }
    }
}

// ---------------- kernel 2: in-degree histogram (4 edges/thread) -----------
__global__ void hist_kernel(const int* __restrict__ dst) {
    int i = blockIdx.x * blockDim.x + threadIdx.x;   // 200000 threads
    if (i * 4 < E_EDGES) {
        int4 d4 = *reinterpret_cast<const int4*>(&dst[i * 4]);
        atomicAdd(&g_deg[d4.x], 1);
        atomicAdd(&g_deg[d4.y], 1);
        atomicAdd(&g_deg[d4.z], 1);
        atomicAdd(&g_deg[d4.w], 1);
    }
}

// ---------------- kernel 3a: per-chunk degree sums (phase 1 of scan) -------
__global__ __launch_bounds__(1024) void scan_reduce_kernel() {
    __shared__ int warp_sums[32];
    const int tid  = threadIdx.x;
    const int lane = tid & 31;
    const int w    = tid >> 5;
    const int i4   = blockIdx.x * SCAN_CHUNK + tid * 4;

    int4 v = make_int4(0, 0, 0, 0);
    if (i4 < N_NODES)   // N_NODES % 4 == 0 -> whole-int4 guard is exact
        v = *reinterpret_cast<const int4*>(&g_deg[i4]);
    int s = v.x + v.y + v.z + v.w;
#pragma unroll
    for (int o = 16; o > 0; o >>= 1) s += __shfl_xor_sync(0xFFFFFFFFu, s, o);
    if (lane == 0) warp_sums[w] = s;
    __syncthreads();
    if (w == 0) {
        int t = warp_sums[lane];
#pragma unroll
        for (int o = 16; o > 0; o >>= 1) t += __shfl_xor_sync(0xFFFFFFFFu, t, o);
        if (lane == 0) g_bsum[blockIdx.x] = t;
    }
}

// ---------------- kernel 3b: per-chunk exclusive scan (phase 2) ------------
__global__ __launch_bounds__(1024) void scan_blocks_kernel() {
    __shared__ int warp_sums[32];
    __shared__ int s_base;
    const int tid  = threadIdx.x;
    const int lane = tid & 31;
    const int w    = tid >> 5;
    const int blk  = blockIdx.x;

    // block base = exclusive prefix of g_bsum over preceding chunks
    if (w == 0) {
        int v = (lane < blk) ? g_bsum[lane] : 0;   // SCAN_BLOCKS=13 <= 32
#pragma unroll
        for (int o = 16; o > 0; o >>= 1) v += __shfl_xor_sync(0xFFFFFFFFu, v, o);
        if (lane == 0) s_base = v;
    }
    if (tid == 0 && blk == 0) g_off[0] = 0;
    __syncthreads();

    const int i4 = blk * SCAN_CHUNK + tid * 4;
    int4 v = make_int4(0, 0, 0, 0);
    if (i4 < N_NODES)
        v = *reinterpret_cast<const int4*>(&g_deg[i4]);
    int tsum = v.x + v.y + v.z + v.w;

    int x = tsum;
#pragma unroll
    for (int o = 1; o < 32; o <<= 1) {
        int y = __shfl_up_sync(0xFFFFFFFFu, x, o);
        if (lane >= o) x += y;
    }
    if (lane == 31) warp_sums[w] = x;
    __syncthreads();
    if (w == 0) {
        int y = warp_sums[lane];
#pragma unroll
        for (int o = 1; o < 32; o <<= 1) {
            int z = __shfl_up_sync(0xFFFFFFFFu, y, o);
            if (lane >= o) y += z;
        }
        warp_sums[lane] = y;
    }
    __syncthreads();

    int excl = (x - tsum) + (w > 0 ? warp_sums[w - 1] : 0) + s_base;
    if (i4 < N_NODES) {
        int p1 = excl + v.x;
        int p2 = p1 + v.y;
        int p3 = p2 + v.z;
        int p4 = p3 + v.w;
        *reinterpret_cast<int4*>(&g_pos[i4]) = make_int4(excl, p1, p2, p3);
        g_off[i4 + 1] = p1;
        g_off[i4 + 2] = p2;
        g_off[i4 + 3] = p3;
        g_off[i4 + 4] = p4;
    }
}

// ---------------- kernel 4: scatter edges into CSR-by-dst (x4) -------------
__global__ void scatter_kernel(const int* __restrict__ src,
                               const int* __restrict__ dst) {
    int i = blockIdx.x * blockDim.x + threadIdx.x;
    if (i * 4 < E_EDGES) {
        int4 d4 = *reinterpret_cast<const int4*>(&dst[i * 4]);
        int4 s4 = *reinterpret_cast<const int4*>(&src[i * 4]);
        g_csr_src[atomicAdd(&g_pos[d4.x], 1)] = s4.x;
        g_csr_src[atomicAdd(&g_pos[d4.y], 1)] = s4.y;
        g_csr_src[atomicAdd(&g_pos[d4.z], 1)] = s4.z;
        g_csr_src[atomicAdd(&g_pos[d4.w], 1)] = s4.w;
    }
}

// ---------------- kernel 5: fused softmax + aggregation, 1 warp / dst ------
// Softmax shift dropped: scores are leaky_relu of small dot sums (|x| << 80),
// exp cannot overflow, and softmax is shift-invariant.
// Software-pipelined: next edge's csr index + el logit prefetched one
// iteration ahead so their L2 latency overlaps the current ft gather.
__global__ __launch_bounds__(256) void agg_kernel(const float* __restrict__ bias,
                                                  float* __restrict__ out) {
    int d    = (blockIdx.x * blockDim.x + threadIdx.x) >> 5;
    int lane = threadIdx.x & 31;
    if (d >= N_NODES) return;

    int start = g_off[d];
    int end   = g_off[d + 1];

    int   h  = lane >> 3;                 // head owning lanes' 4 output dims
    float er = g_er[d * H_HEADS + h];

    float4 acc  = make_float4(0.f, 0.f, 0.f, 0.f);
    float  ssum = 0.f;

    int   s_nx  = 0;
    float el_nx = 0.f;
    if (start < end) {
        s_nx  = g_csr_src[start];
        el_nx = g_el[s_nx * H_HEADS + h];
    }
    for (int j = start; j < end; ++j) {
        int   s   = s_nx;
        float elv = el_nx;
        int   jn  = j + 1;
        if (jn < end) {
            s_nx  = g_csr_src[jn];
            el_nx = g_el[s_nx * H_HEADS + h];
        }
        float4 f = *reinterpret_cast<const float4*>(
            &g_ft[(size_t)s * M_OUT + lane * 4]);
        float x = elv + er;
        x = (x > 0.f) ? x : NEG_SLOPE * x;
        float a = __expf(x);              // same across the 8 lanes of a head
        ssum += a;
        acc.x += f.x * a; acc.y += f.y * a; acc.z += f.z * a; acc.w += f.w * a;
    }
    float inv = (end > start) ? 1.f / ssum : 0.f;

    float4 b = *reinterpret_cast<const float4*>(&bias[lane * 4]);
    float4 o;
    o.x = acc.x * inv + b.x;
    o.y = acc.y * inv + b.y;
    o.z = acc.z * inv + b.z;
    o.w = acc.w * inv + b.w;
    *reinterpret_cast<float4*>(&out[(size_t)d * M_OUT + lane * 4]) = o;
}

// ---------------- launch ----------------------------------------------------
extern "C" void kernel_launch(void* const* d_in, const int* in_sizes, int n_in,
                              void* d_out, int out_size) {
    const float* feat   = (const float*)d_in[0];
    const int*   src    = (const int*)d_in[1];
    const int*   dst    = (const int*)d_in[2];
    const float* W      = (const float*)d_in[3];
    const float* attn_l = (const float*)d_in[4];
    const float* attn_r = (const float*)d_in[5];
    const float* bias   = (const float*)d_in[6];
    float* out = (float*)d_out;

    zero_kernel<<<(N_NODES / 4 + 255) / 256, 256>>>();
    gemm_kernel<<<(N_NODES + BR - 1) / BR, 256>>>(feat, W, attn_l, attn_r);
    hist_kernel<<<(E_EDGES / 4 + 255) / 256, 256>>>(dst);
    scan_reduce_kernel<<<SCAN_BLOCKS, 1024>>>();
    scan_blocks_kernel<<<SCAN_BLOCKS, 1024>>>();
    scatter_kernel<<<(E_EDGES / 4 + 255) / 256, 256>>>(src, dst);
    agg_kernel<<<(N_NODES + 7) / 8, 256>>>(bias, out);
}

// round 16
// speedup vs baseline: 1.0566x; 1.0554x over previous
#include <cuda_runtime.h>
#include <cuda_bf16.h>
#include <math.h>

// Problem constants (match reference)
#define N_NODES 50000
#define E_EDGES 800000
#define K_IN    256
#define M_OUT   128   // H*D = 4*32
#define H_HEADS 4
#define D_HEAD  32
#define NEG_SLOPE 0.2f

#define SCAN_CHUNK 4096
#define SCAN_BLOCKS ((N_NODES + SCAN_CHUNK - 1) / SCAN_CHUNK)   // 13

typedef unsigned long long ull;

// ---------------- scratch (device globals; no allocation allowed) ----------
// NOTE: zero-initialized at module load; scan_blocks_kernel re-zeroes g_deg
// after consuming it, so every kernel_launch call sees a clean histogram.
__device__ float g_ft[(size_t)N_NODES * M_OUT];   // projected features [N,128]
__device__ float g_el[N_NODES * H_HEADS];         // per-node left logits
__device__ float g_er[N_NODES * H_HEADS];         // per-node right logits
__device__ int   g_deg[N_NODES];
__device__ int   g_pos[N_NODES];                  // running fill cursor (init = offsets)
__device__ int   g_off[N_NODES + 1];
__device__ int   g_csr_src[E_EDGES];
__device__ int   g_bsum[SCAN_BLOCKS];             // per-chunk sums for 2-phase scan

// ---------------- f32x2 packed-FMA helpers (sm_100+) ----------------------
__device__ __forceinline__ ull pack2(float x, float y) {
    ull r;
    asm("mov.b64 %0, {%1,%2};" : "=l"(r) : "f"(x), "f"(y));
    return r;
}
__device__ __forceinline__ void unpack2(ull v, float& x, float& y) {
    asm("mov.b64 {%0,%1}, %2;" : "=f"(x), "=f"(y) : "l"(v));
}
__device__ __forceinline__ void ffma2(ull& d, ull a, ull b) {
    asm("fma.rn.f32x2 %0, %1, %2, %0;" : "+l"(d) : "l"(a), "l"(b));
}

// ---------------- kernel 1: in-degree histogram (4 edges/thread) -----------
__global__ void hist_kernel(const int* __restrict__ dst) {
    int i = blockIdx.x * blockDim.x + threadIdx.x;   // 200000 threads
    if (i * 4 < E_EDGES) {
        int4 d4 = *reinterpret_cast<const int4*>(&dst[i * 4]);
        atomicAdd(&g_deg[d4.x], 1);
        atomicAdd(&g_deg[d4.y], 1);
        atomicAdd(&g_deg[d4.z], 1);
        atomicAdd(&g_deg[d4.w], 1);
    }
}

// ---------------- kernel 2: per-chunk degree sums (phase 1 of scan) --------
__global__ __launch_bounds__(1024) void scan_reduce_kernel() {
    __shared__ int warp_sums[32];
    const int tid  = threadIdx.x;
    const int lane = tid & 31;
    const int w    = tid >> 5;
    const int i4   = blockIdx.x * SCAN_CHUNK + tid * 4;

    int4 v = make_int4(0, 0, 0, 0);
    if (i4 < N_NODES)   // N_NODES % 4 == 0 -> whole-int4 guard is exact
        v = *reinterpret_cast<const int4*>(&g_deg[i4]);
    int s = v.x + v.y + v.z + v.w;
#pragma unroll
    for (int o = 16; o > 0; o >>= 1) s += __shfl_xor_sync(0xFFFFFFFFu, s, o);
    if (lane == 0) warp_sums[w] = s;
    __syncthreads();
    if (w == 0) {
        int t = warp_sums[lane];
#pragma unroll
        for (int o = 16; o > 0; o >>= 1) t += __shfl_xor_sync(0xFFFFFFFFu, t, o);
        if (lane == 0) g_bsum[blockIdx.x] = t;
    }
}

// ---------------- kernel 3: per-chunk exclusive scan (phase 2) -------------
// Also re-zeroes g_deg after reading it, so the next kernel_launch call's
// histogram starts clean without a separate zero kernel.
__global__ __launch_bounds__(1024) void scan_blocks_kernel() {
    __shared__ int warp_sums[32];
    __shared__ int s_base;
    const int tid  = threadIdx.x;
    const int lane = tid & 31;
    const int w    = tid >> 5;
    const int blk  = blockIdx.x;

    // block base = exclusive prefix of g_bsum over preceding chunks
    if (w == 0) {
        int v = (lane < blk) ? g_bsum[lane] : 0;   // SCAN_BLOCKS=13 <= 32
#pragma unroll
        for (int o = 16; o > 0; o >>= 1) v += __shfl_xor_sync(0xFFFFFFFFu, v, o);
        if (lane == 0) s_base = v;
    }
    if (tid == 0 && blk == 0) g_off[0] = 0;
    __syncthreads();

    const int i4 = blk * SCAN_CHUNK + tid * 4;
    int4 v = make_int4(0, 0, 0, 0);
    if (i4 < N_NODES) {
        v = *reinterpret_cast<const int4*>(&g_deg[i4]);
        *reinterpret_cast<int4*>(&g_deg[i4]) = make_int4(0, 0, 0, 0);  // reset
    }
    int tsum = v.x + v.y + v.z + v.w;

    int x = tsum;
#pragma unroll
    for (int o = 1; o < 32; o <<= 1) {
        int y = __shfl_up_sync(0xFFFFFFFFu, x, o);
        if (lane >= o) x += y;
    }
    if (lane == 31) warp_sums[w] = x;
    __syncthreads();
    if (w == 0) {
        int y = warp_sums[lane];
#pragma unroll
        for (int o = 1; o < 32; o <<= 1) {
            int z = __shfl_up_sync(0xFFFFFFFFu, y, o);
            if (lane >= o) y += z;
        }
        warp_sums[lane] = y;
    }
    __syncthreads();

    int excl = (x - tsum) + (w > 0 ? warp_sums[w - 1] : 0) + s_base;
    if (i4 < N_NODES) {
        int p1 = excl + v.x;
        int p2 = p1 + v.y;
        int p3 = p2 + v.z;
        int p4 = p3 + v.w;
        *reinterpret_cast<int4*>(&g_pos[i4]) = make_int4(excl, p1, p2, p3);
        g_off[i4 + 1] = p1;
        g_off[i4 + 2] = p2;
        g_off[i4 + 3] = p3;
        g_off[i4 + 4] = p4;
    }
}

// ---------------- kernel 4: GEMM ft = feat @ W + fused el/er ---------------
// 64 rows x 128 cols per block, 256 threads.
// warp ty owns rows ty*8..ty*8+7; lane tx owns cols tx*4..tx*4+3.
// A tile in smem as duplicated (a,a) f32x2 pairs -> broadcast LDS.128.
// B tile read as native f32x2 pairs (adjacent cols) -> no packing.
// Register double-buffered: next k-tile's gmem loads issue before compute.
#define BR 64
#define KC 32
#define BS_LD 132

__global__ __launch_bounds__(256) void gemm_kernel(const float* __restrict__ A,
                                                   const float* __restrict__ B,
                                                   const float* __restrict__ attn_l,
                                                   const float* __restrict__ attn_r) {
    __shared__ ull   As2[KC][BR];      // 16 KB, [k][row] duplicated pairs
    __shared__ float Bs[KC][BS_LD];    // ~16.9 KB

    const int tid  = threadIdx.x;
    const int row0 = blockIdx.x * BR;
    const int ty   = tid >> 5;   // 0..7
    const int tx   = tid & 31;   // 0..31

    // attn slices for fused epilogue
    const float4 al = *reinterpret_cast<const float4*>(&attn_l[tx * 4]);
    const float4 ar = *reinterpret_cast<const float4*>(&attn_r[tx * 4]);

    ull acc[8][2];
#pragma unroll
    for (int i = 0; i < 8; i++) { acc[i][0] = 0ULL; acc[i][1] = 0ULL; }

    // A fill: row = tid>>2 (0..63), k offsets (tid&3)*8 .. +7  (8 floats/thread)
    const int a_r = tid >> 2;
    const int a_k = (tid & 3) * 8;
    const int a_gr = row0 + a_r;
    // B fill: k row = tid>>3 (0..31), col base (tid&7)*16 (16 floats/thread)
    const int b_k = tid >> 3;
    const int b_c = (tid & 7) * 16;

    float4 v0, v1, w0, w1, w2, w3;

    // prologue load (k0 = 0)
    {
        v0 = make_float4(0.f, 0.f, 0.f, 0.f); v1 = v0;
        if (a_gr < N_NODES) {
            const float* ap = &A[(size_t)a_gr * K_IN + a_k];
            v0 = *reinterpret_cast<const float4*>(ap);
            v1 = *reinterpret_cast<const float4*>(ap + 4);
        }
        const float* bp = &B[(size_t)b_k * M_OUT + b_c];
        w0 = *reinterpret_cast<const float4*>(bp);
        w1 = *reinterpret_cast<const float4*>(bp + 4);
        w2 = *reinterpret_cast<const float4*>(bp + 8);
        w3 = *reinterpret_cast<const float4*>(bp + 12);
    }

    for (int k0 = 0; k0 < K_IN; k0 += KC) {
        // stage current regs -> smem
        As2[a_k + 0][a_r] = pack2(v0.x, v0.x);
        As2[a_k + 1][a_r] = pack2(v0.y, v0.y);
        As2[a_k + 2][a_r] = pack2(v0.z, v0.z);
        As2[a_k + 3][a_r] = pack2(v0.w, v0.w);
        As2[a_k + 4][a_r] = pack2(v1.x, v1.x);
        As2[a_k + 5][a_r] = pack2(v1.y, v1.y);
        As2[a_k + 6][a_r] = pack2(v1.z, v1.z);
        As2[a_k + 7][a_r] = pack2(v1.w, v1.w);
        *reinterpret_cast<float4*>(&Bs[b_k][b_c])      = w0;
        *reinterpret_cast<float4*>(&Bs[b_k][b_c + 4])  = w1;
        *reinterpret_cast<float4*>(&Bs[b_k][b_c + 8])  = w2;
        *reinterpret_cast<float4*>(&Bs[b_k][b_c + 12]) = w3;
        __syncthreads();

        // prefetch next tile while computing this one
        int kn = k0 + KC;
        if (kn < K_IN) {
            v0 = make_float4(0.f, 0.f, 0.f, 0.f); v1 = v0;
            if (a_gr < N_NODES) {
                const float* ap = &A[(size_t)a_gr * K_IN + kn + a_k];
                v0 = *reinterpret_cast<const float4*>(ap);
                v1 = *reinterpret_cast<const float4*>(ap + 4);
            }
            const float* bp = &B[(size_t)(kn + b_k) * M_OUT + b_c];
            w0 = *reinterpret_cast<const float4*>(bp);
            w1 = *reinterpret_cast<const float4*>(bp + 4);
            w2 = *reinterpret_cast<const float4*>(bp + 8);
            w3 = *reinterpret_cast<const float4*>(bp + 12);
        }

#pragma unroll
        for (int k = 0; k < KC; k++) {
            ulonglong2 bb = *reinterpret_cast<const ulonglong2*>(&Bs[k][tx * 4]);
            const ulonglong2* arow =
                reinterpret_cast<const ulonglong2*>(&As2[k][ty * 8]);
            ulonglong2 a01 = arow[0];
            ulonglong2 a23 = arow[1];
            ulonglong2 a45 = arow[2];
            ulonglong2 a67 = arow[3];
            ffma2(acc[0][0], a01.x, bb.x); ffma2(acc[0][1], a01.x, bb.y);
            ffma2(acc[1][0], a01.y, bb.x); ffma2(acc[1][1], a01.y, bb.y);
            ffma2(acc[2][0], a23.x, bb.x); ffma2(acc[2][1], a23.x, bb.y);
            ffma2(acc[3][0], a23.y, bb.x); ffma2(acc[3][1], a23.y, bb.y);
            ffma2(acc[4][0], a45.x, bb.x); ffma2(acc[4][1], a45.x, bb.y);
            ffma2(acc[5][0], a45.y, bb.x); ffma2(acc[5][1], a45.y, bb.y);
            ffma2(acc[6][0], a67.x, bb.x); ffma2(acc[6][1], a67.x, bb.y);
            ffma2(acc[7][0], a67.y, bb.x); ffma2(acc[7][1], a67.y, bb.y);
        }
        __syncthreads();
    }

    // epilogue: store ft rows + fused el/er (dot with attn over 8-lane head groups)
#pragma unroll
    for (int i = 0; i < 8; i++) {
        int gr = row0 + ty * 8 + i;
        if (gr < N_NODES) {
            float4 o;
            unpack2(acc[i][0], o.x, o.y);
            unpack2(acc[i][1], o.z, o.w);
            *reinterpret_cast<float4*>(&g_ft[(size_t)gr * M_OUT + tx * 4]) = o;

            float pl = o.x * al.x + o.y * al.y + o.z * al.z + o.w * al.w;
            float pr = o.x * ar.x + o.y * ar.y + o.z * ar.z + o.w * ar.w;
#pragma unroll
            for (int off = 1; off < 8; off <<= 1) {
                pl += __shfl_xor_sync(0xFFFFFFFFu, pl, off);
                pr += __shfl_xor_sync(0xFFFFFFFFu, pr, off);
            }
            if ((tx & 7) == 0) {
                g_el[gr * H_HEADS + (tx >> 3)] = pl;
                g_er[gr * H_HEADS + (tx >> 3)] = pr;
            }
        }
    }
}

// ---------------- kernel 5: scatter edges into CSR-by-dst (x4) -------------
__global__ void scatter_kernel(const int* __restrict__ src,
                               const int* __restrict__ dst) {
    int i = blockIdx.x * blockDim.x + threadIdx.x;
    if (i * 4 < E_EDGES) {
        int4 d4 = *reinterpret_cast<const int4*>(&dst[i * 4]);
        int4 s4 = *reinterpret_cast<const int4*>(&src[i * 4]);
        g_csr_src[atomicAdd(&g_pos[d4.x], 1)] = s4.x;
        g_csr_src[atomicAdd(&g_pos[d4.y], 1)] = s4.y;
        g_csr_src[atomicAdd(&g_pos[d4.z], 1)] = s4.z;
        g_csr_src[atomicAdd(&g_pos[d4.w], 1)] = s4.w;
    }
}

// ---------------- kernel 6: fused softmax + aggregation, 1 warp / dst ------
// Softmax shift dropped: scores are leaky_relu of small dot sums (|x| << 80),
// exp cannot overflow, and softmax is shift-invariant.
// 2-edge unroll: two independent ft gathers in flight per iteration.
__global__ __launch_bounds__(256) void agg_kernel(const float* __restrict__ bias,
                                                  float* __restrict__ out) {
    int d    = (blockIdx.x * blockDim.x + threadIdx.x) >> 5;
    int lane = threadIdx.x & 31;
    if (d >= N_NODES) return;

    int start = g_off[d];
    int end   = g_off[d + 1];

    int   h  = lane >> 3;                 // head owning lanes' 4 output dims
    float er = g_er[d * H_HEADS + h];

    float4 acc  = make_float4(0.f, 0.f, 0.f, 0.f);
    float  ssum = 0.f;

    int j = start;
    for (; j + 1 < end; j += 2) {
        int s0 = g_csr_src[j];
        int s1 = g_csr_src[j + 1];
        float el0 = g_el[s0 * H_HEADS + h];
        float el1 = g_el[s1 * H_HEADS + h];
        float4 f0 = *reinterpret_cast<const float4*>(
            &g_ft[(size_t)s0 * M_OUT + lane * 4]);
        float4 f1 = *reinterpret_cast<const float4*>(
            &g_ft[(size_t)s1 * M_OUT + lane * 4]);
        float x0 = el0 + er; x0 = (x0 > 0.f) ? x0 : NEG_SLOPE * x0;
        float x1 = el1 + er; x1 = (x1 > 0.f) ? x1 : NEG_SLOPE * x1;
        float a0 = __expf(x0);
        float a1 = __expf(x1);
        ssum += a0 + a1;
        acc.x += f0.x * a0 + f1.x * a1;
        acc.y += f0.y * a0 + f1.y * a1;
        acc.z += f0.z * a0 + f1.z * a1;
        acc.w += f0.w * a0 + f1.w * a1;
    }
    if (j < end) {
        int s = g_csr_src[j];
        float x = g_el[s * H_HEADS + h] + er;
        x = (x > 0.f) ? x : NEG_SLOPE * x;
        float a = __expf(x);
        ssum += a;
        float4 f = *reinterpret_cast<const float4*>(
            &g_ft[(size_t)s * M_OUT + lane * 4]);
        acc.x += f.x * a; acc.y += f.y * a; acc.z += f.z * a; acc.w += f.w * a;
    }
    float inv = (end > start) ? 1.f / ssum : 0.f;

    float4 b = *reinterpret_cast<const float4*>(&bias[lane * 4]);
    float4 o;
    o.x = acc.x * inv + b.x;
    o.y = acc.y * inv + b.y;
    o.z = acc.z * inv + b.z;
    o.w = acc.w * inv + b.w;
    *reinterpret_cast<float4*>(&out[(size_t)d * M_OUT + lane * 4]) = o;
}

// ---------------- launch ----------------------------------------------------
// Order puts gemm_kernel at launch position 4 (the one ncu captures) while
// respecting dependencies: gemm is independent of the CSR build.
extern "C" void kernel_launch(void* const* d_in, const int* in_sizes, int n_in,
                              void* d_out, int out_size) {
    const float* feat   = (const float*)d_in[0];
    const int*   src    = (const int*)d_in[1];
    const int*   dst    = (const int*)d_in[2];
    const float* W      = (const float*)d_in[3];
    const float* attn_l = (const float*)d_in[4];
    const float* attn_r = (const float*)d_in[5];
    const float* bias   = (const float*)d_in[6];
    float* out = (float*)d_out;

    hist_kernel<<<(E_EDGES / 4 + 255) / 256, 256>>>(dst);
    scan_reduce_kernel<<<SCAN_BLOCKS, 1024>>>();
    scan_blocks_kernel<<<SCAN_BLOCKS, 1024>>>();
    gemm_kernel<<<(N_NODES + BR - 1) / BR, 256>>>(feat, W, attn_l, attn_r);
    scatter_kernel<<<(E_EDGES / 4 + 255) / 256, 256>>>(src, dst);
    agg_kernel<<<(N_NODES + 7) / 8, 256>>>(bias, out);
}

// round 17
// speedup vs baseline: 1.0747x; 1.0171x over previous
#include <cuda_runtime.h>
#include <cuda_bf16.h>
#include <math.h>

// Problem constants (match reference)
#define N_NODES 50000
#define E_EDGES 800000
#define K_IN    256
#define M_OUT   128   // H*D = 4*32
#define H_HEADS 4
#define D_HEAD  32
#define NEG_SLOPE 0.2f

#define SCAN_CHUNK 4096
#define SCAN_BLOCKS ((N_NODES + SCAN_CHUNK - 1) / SCAN_CHUNK)   // 13

typedef unsigned long long ull;

// ---------------- scratch (device globals; no allocation allowed) ----------
// NOTE: zero-initialized at module load; scan_blocks_kernel re-zeroes g_deg
// after consuming it, so every kernel_launch call sees a clean histogram.
__device__ float g_ft[(size_t)N_NODES * M_OUT];   // projected features [N,128]
__device__ float g_el[N_NODES * H_HEADS];         // per-node left logits
__device__ float g_er[N_NODES * H_HEADS];         // per-node right logits
__device__ int   g_deg[N_NODES];
__device__ int   g_pos[N_NODES];                  // running fill cursor (init = offsets)
__device__ int   g_off[N_NODES + 1];
__device__ int   g_csr_src[E_EDGES];
__device__ int   g_bsum[SCAN_BLOCKS];             // per-chunk sums for 2-phase scan

// ---------------- f32x2 packed-FMA helpers (sm_100+) ----------------------
__device__ __forceinline__ ull pack2(float x, float y) {
    ull r;
    asm("mov.b64 %0, {%1,%2};" : "=l"(r) : "f"(x), "f"(y));
    return r;
}
__device__ __forceinline__ void unpack2(ull v, float& x, float& y) {
    asm("mov.b64 {%0,%1}, %2;" : "=f"(x), "=f"(y) : "l"(v));
}
__device__ __forceinline__ void ffma2(ull& d, ull a, ull b) {
    asm("fma.rn.f32x2 %0, %1, %2, %0;" : "+l"(d) : "l"(a), "l"(b));
}

// ---------------- kernel 1: in-degree histogram (4 edges/thread) -----------
__global__ void hist_kernel(const int* __restrict__ dst) {
    int i = blockIdx.x * blockDim.x + threadIdx.x;   // 200000 threads
    if (i * 4 < E_EDGES) {
        int4 d4 = *reinterpret_cast<const int4*>(&dst[i * 4]);
        atomicAdd(&g_deg[d4.x], 1);
        atomicAdd(&g_deg[d4.y], 1);
        atomicAdd(&g_deg[d4.z], 1);
        atomicAdd(&g_deg[d4.w], 1);
    }
}

// ---------------- kernel 2: per-chunk degree sums (phase 1 of scan) --------
__global__ __launch_bounds__(1024) void scan_reduce_kernel() {
    __shared__ int warp_sums[32];
    const int tid  = threadIdx.x;
    const int lane = tid & 31;
    const int w    = tid >> 5;
    const int i4   = blockIdx.x * SCAN_CHUNK + tid * 4;

    int4 v = make_int4(0, 0, 0, 0);
    if (i4 < N_NODES)   // N_NODES % 4 == 0 -> whole-int4 guard is exact
        v = *reinterpret_cast<const int4*>(&g_deg[i4]);
    int s = v.x + v.y + v.z + v.w;
#pragma unroll
    for (int o = 16; o > 0; o >>= 1) s += __shfl_xor_sync(0xFFFFFFFFu, s, o);
    if (lane == 0) warp_sums[w] = s;
    __syncthreads();
    if (w == 0) {
        int t = warp_sums[lane];
#pragma unroll
        for (int o = 16; o > 0; o >>= 1) t += __shfl_xor_sync(0xFFFFFFFFu, t, o);
        if (lane == 0) g_bsum[blockIdx.x] = t;
    }
}

// ---------------- kernel 3: per-chunk exclusive scan (phase 2) -------------
// Also re-zeroes g_deg after reading it, so the next kernel_launch call's
// histogram starts clean without a separate zero kernel.
__global__ __launch_bounds__(1024) void scan_blocks_kernel() {
    __shared__ int warp_sums[32];
    __shared__ int s_base;
    const int tid  = threadIdx.x;
    const int lane = tid & 31;
    const int w    = tid >> 5;
    const int blk  = blockIdx.x;

    // block base = exclusive prefix of g_bsum over preceding chunks
    if (w == 0) {
        int v = (lane < blk) ? g_bsum[lane] : 0;   // SCAN_BLOCKS=13 <= 32
#pragma unroll
        for (int o = 16; o > 0; o >>= 1) v += __shfl_xor_sync(0xFFFFFFFFu, v, o);
        if (lane == 0) s_base = v;
    }
    if (tid == 0 && blk == 0) g_off[0] = 0;
    __syncthreads();

    const int i4 = blk * SCAN_CHUNK + tid * 4;
    int4 v = make_int4(0, 0, 0, 0);
    if (i4 < N_NODES) {
        v = *reinterpret_cast<const int4*>(&g_deg[i4]);
        *reinterpret_cast<int4*>(&g_deg[i4]) = make_int4(0, 0, 0, 0);  // reset
    }
    int tsum = v.x + v.y + v.z + v.w;

    int x = tsum;
#pragma unroll
    for (int o = 1; o < 32; o <<= 1) {
        int y = __shfl_up_sync(0xFFFFFFFFu, x, o);
        if (lane >= o) x += y;
    }
    if (lane == 31) warp_sums[w] = x;
    __syncthreads();
    if (w == 0) {
        int y = warp_sums[lane];
#pragma unroll
        for (int o = 1; o < 32; o <<= 1) {
            int z = __shfl_up_sync(0xFFFFFFFFu, y, o);
            if (lane >= o) y += z;
        }
        warp_sums[lane] = y;
    }
    __syncthreads();

    int excl = (x - tsum) + (w > 0 ? warp_sums[w - 1] : 0) + s_base;
    if (i4 < N_NODES) {
        int p1 = excl + v.x;
        int p2 = p1 + v.y;
        int p3 = p2 + v.z;
        int p4 = p3 + v.w;
        *reinterpret_cast<int4*>(&g_pos[i4]) = make_int4(excl, p1, p2, p3);
        g_off[i4 + 1] = p1;
        g_off[i4 + 2] = p2;
        g_off[i4 + 3] = p3;
        g_off[i4 + 4] = p4;
    }
}

// ---------------- kernel 4: GEMM ft = feat @ W + fused el/er ---------------
// 128 rows x 128 cols per 256-thread block, KC=16.
// Warp w owns rows w*16..w*16+15 (16 rows/thread); lane tx owns cols tx*4..+3.
// Per k: 8 broadcast LDS.128 (A pairs) + 1 distinct LDS.128 (B) feed 32 FFMA2
// -> FMA-bound (was LDS-bound at 8 rows/thread).
#define BR 128
#define KC 16
#define BS_LD 132

__global__ __launch_bounds__(256) void gemm_kernel(const float* __restrict__ A,
                                                   const float* __restrict__ B,
                                                   const float* __restrict__ attn_l,
                                                   const float* __restrict__ attn_r) {
    __shared__ ull   As2[KC][BR];      // 16 KB, [k][row] duplicated (a,a) pairs
    __shared__ float Bs[KC][BS_LD];    // ~8.4 KB

    const int tid  = threadIdx.x;
    const int row0 = blockIdx.x * BR;
    const int w16  = (tid >> 5) * 16;  // warp's first row within tile
    const int tx   = tid & 31;

    ull acc[16][2];
#pragma unroll
    for (int i = 0; i < 16; i++) { acc[i][0] = 0ULL; acc[i][1] = 0ULL; }

    // A staging: row = tid>>1 (0..127), k offsets (tid&1)*8 .. +7 (8 floats)
    const int a_r  = tid >> 1;
    const int a_k  = (tid & 1) * 8;
    const int a_gr = row0 + a_r;
    // B staging: k row = tid>>4 (0..15), col base (tid&15)*8 (8 floats)
    const int b_k = tid >> 4;
    const int b_c = (tid & 15) * 8;

    float4 v0, v1, w0, w1;

    // prologue load (k0 = 0)
    {
        v0 = make_float4(0.f, 0.f, 0.f, 0.f); v1 = v0;
        if (a_gr < N_NODES) {
            const float* ap = &A[(size_t)a_gr * K_IN + a_k];
            v0 = *reinterpret_cast<const float4*>(ap);
            v1 = *reinterpret_cast<const float4*>(ap + 4);
        }
        const float* bp = &B[(size_t)b_k * M_OUT + b_c];
        w0 = *reinterpret_cast<const float4*>(bp);
        w1 = *reinterpret_cast<const float4*>(bp + 4);
    }

    for (int k0 = 0; k0 < K_IN; k0 += KC) {
        // stage current regs -> smem
        As2[a_k + 0][a_r] = pack2(v0.x, v0.x);
        As2[a_k + 1][a_r] = pack2(v0.y, v0.y);
        As2[a_k + 2][a_r] = pack2(v0.z, v0.z);
        As2[a_k + 3][a_r] = pack2(v0.w, v0.w);
        As2[a_k + 4][a_r] = pack2(v1.x, v1.x);
        As2[a_k + 5][a_r] = pack2(v1.y, v1.y);
        As2[a_k + 6][a_r] = pack2(v1.z, v1.z);
        As2[a_k + 7][a_r] = pack2(v1.w, v1.w);
        *reinterpret_cast<float4*>(&Bs[b_k][b_c])     = w0;
        *reinterpret_cast<float4*>(&Bs[b_k][b_c + 4]) = w1;
        __syncthreads();

        // prefetch next tile while computing this one
        int kn = k0 + KC;
        if (kn < K_IN) {
            v0 = make_float4(0.f, 0.f, 0.f, 0.f); v1 = v0;
            if (a_gr < N_NODES) {
                const float* ap = &A[(size_t)a_gr * K_IN + kn + a_k];
                v0 = *reinterpret_cast<const float4*>(ap);
                v1 = *reinterpret_cast<const float4*>(ap + 4);
            }
            const float* bp = &B[(size_t)(kn + b_k) * M_OUT + b_c];
            w0 = *reinterpret_cast<const float4*>(bp);
            w1 = *reinterpret_cast<const float4*>(bp + 4);
        }

#pragma unroll
        for (int k = 0; k < KC; k++) {
            ulonglong2 bb = *reinterpret_cast<const ulonglong2*>(&Bs[k][tx * 4]);
            const ulonglong2* ap =
                reinterpret_cast<const ulonglong2*>(&As2[k][w16]);
            ulonglong2 p;
            p = ap[0];
            ffma2(acc[0][0],  p.x, bb.x); ffma2(acc[0][1],  p.x, bb.y);
            ffma2(acc[1][0],  p.y, bb.x); ffma2(acc[1][1],  p.y, bb.y);
            p = ap[1];
            ffma2(acc[2][0],  p.x, bb.x); ffma2(acc[2][1],  p.x, bb.y);
            ffma2(acc[3][0],  p.y, bb.x); ffma2(acc[3][1],  p.y, bb.y);
            p = ap[2];
            ffma2(acc[4][0],  p.x, bb.x); ffma2(acc[4][1],  p.x, bb.y);
            ffma2(acc[5][0],  p.y, bb.x); ffma2(acc[5][1],  p.y, bb.y);
            p = ap[3];
            ffma2(acc[6][0],  p.x, bb.x); ffma2(acc[6][1],  p.x, bb.y);
            ffma2(acc[7][0],  p.y, bb.x); ffma2(acc[7][1],  p.y, bb.y);
            p = ap[4];
            ffma2(acc[8][0],  p.x, bb.x); ffma2(acc[8][1],  p.x, bb.y);
            ffma2(acc[9][0],  p.y, bb.x); ffma2(acc[9][1],  p.y, bb.y);
            p = ap[5];
            ffma2(acc[10][0], p.x, bb.x); ffma2(acc[10][1], p.x, bb.y);
            ffma2(acc[11][0], p.y, bb.x); ffma2(acc[11][1], p.y, bb.y);
            p = ap[6];
            ffma2(acc[12][0], p.x, bb.x); ffma2(acc[12][1], p.x, bb.y);
            ffma2(acc[13][0], p.y, bb.x); ffma2(acc[13][1], p.y, bb.y);
            p = ap[7];
            ffma2(acc[14][0], p.x, bb.x); ffma2(acc[14][1], p.x, bb.y);
            ffma2(acc[15][0], p.y, bb.x); ffma2(acc[15][1], p.y, bb.y);
        }
        __syncthreads();
    }

    // epilogue: store ft rows + fused el/er (loaded here to cut mainloop regs)
    const float4 al = *reinterpret_cast<const float4*>(&attn_l[tx * 4]);
    const float4 ar = *reinterpret_cast<const float4*>(&attn_r[tx * 4]);
#pragma unroll
    for (int i = 0; i < 16; i++) {
        int gr = row0 + w16 + i;
        if (gr < N_NODES) {
            float4 o;
            unpack2(acc[i][0], o.x, o.y);
            unpack2(acc[i][1], o.z, o.w);
            *reinterpret_cast<float4*>(&g_ft[(size_t)gr * M_OUT + tx * 4]) = o;

            float pl = o.x * al.x + o.y * al.y + o.z * al.z + o.w * al.w;
            float pr = o.x * ar.x + o.y * ar.y + o.z * ar.z + o.w * ar.w;
#pragma unroll
            for (int off = 1; off < 8; off <<= 1) {
                pl += __shfl_xor_sync(0xFFFFFFFFu, pl, off);
                pr += __shfl_xor_sync(0xFFFFFFFFu, pr, off);
            }
            if ((tx & 7) == 0) {
                g_el[gr * H_HEADS + (tx >> 3)] = pl;
                g_er[gr * H_HEADS + (tx >> 3)] = pr;
            }
        }
    }
}

// ---------------- kernel 5: scatter edges into CSR-by-dst (x4) -------------
__global__ void scatter_kernel(const int* __restrict__ src,
                               const int* __restrict__ dst) {
    int i = blockIdx.x * blockDim.x + threadIdx.x;
    if (i * 4 < E_EDGES) {
        int4 d4 = *reinterpret_cast<const int4*>(&dst[i * 4]);
        int4 s4 = *reinterpret_cast<const int4*>(&src[i * 4]);
        g_csr_src[atomicAdd(&g_pos[d4.x], 1)] = s4.x;
        g_csr_src[atomicAdd(&g_pos[d4.y], 1)] = s4.y;
        g_csr_src[atomicAdd(&g_pos[d4.z], 1)] = s4.z;
        g_csr_src[atomicAdd(&g_pos[d4.w], 1)] = s4.w;
    }
}

// ---------------- kernel 6: fused softmax + aggregation, 1 warp / dst ------
// Softmax shift dropped: scores are leaky_relu of small dot sums (|x| << 80),
// exp cannot overflow, and softmax is shift-invariant.
// 2-edge unroll: two independent ft gathers in flight per iteration.
__global__ __launch_bounds__(256) void agg_kernel(const float* __restrict__ bias,
                                                  float* __restrict__ out) {
    int d    = (blockIdx.x * blockDim.x + threadIdx.x) >> 5;
    int lane = threadIdx.x & 31;
    if (d >= N_NODES) return;

    int start = g_off[d];
    int end   = g_off[d + 1];

    int   h  = lane >> 3;                 // head owning lanes' 4 output dims
    float er = g_er[d * H_HEADS + h];

    float4 acc  = make_float4(0.f, 0.f, 0.f, 0.f);
    float  ssum = 0.f;

    int j = start;
    for (; j + 1 < end; j += 2) {
        int s0 = g_csr_src[j];
        int s1 = g_csr_src[j + 1];
        float el0 = g_el[s0 * H_HEADS + h];
        float el1 = g_el[s1 * H_HEADS + h];
        float4 f0 = *reinterpret_cast<const float4*>(
            &g_ft[(size_t)s0 * M_OUT + lane * 4]);
        float4 f1 = *reinterpret_cast<const float4*>(
            &g_ft[(size_t)s1 * M_OUT + lane * 4]);
        float x0 = el0 + er; x0 = (x0 > 0.f) ? x0 : NEG_SLOPE * x0;
        float x1 = el1 + er; x1 = (x1 > 0.f) ? x1 : NEG_SLOPE * x1;
        float a0 = __expf(x0);
        float a1 = __expf(x1);
        ssum += a0 + a1;
        acc.x += f0.x * a0 + f1.x * a1;
        acc.y += f0.y * a0 + f1.y * a1;
        acc.z += f0.z * a0 + f1.z * a1;
        acc.w += f0.w * a0 + f1.w * a1;
    }
    if (j < end) {
        int s = g_csr_src[j];
        float x = g_el[s * H_HEADS + h] + er;
        x = (x > 0.f) ? x : NEG_SLOPE * x;
        float a = __expf(x);
        ssum += a;
        float4 f = *reinterpret_cast<const float4*>(
            &g_ft[(size_t)s * M_OUT + lane * 4]);
        acc.x += f.x * a; acc.y += f.y * a; acc.z += f.z * a; acc.w += f.w * a;
    }
    float inv = (end > start) ? 1.f / ssum : 0.f;

    float4 b = *reinterpret_cast<const float4*>(&bias[lane * 4]);
    float4 o;
    o.x = acc.x * inv + b.x;
    o.y = acc.y * inv + b.y;
    o.z = acc.z * inv + b.z;
    o.w = acc.w * inv + b.w;
    *reinterpret_cast<float4*>(&out[(size_t)d * M_OUT + lane * 4]) = o;
}

// ---------------- launch ----------------------------------------------------
// gemm_kernel stays at launch position 4 (the one ncu captures) to verify the
// LDS->FMA bottleneck flip.
extern "C" void kernel_launch(void* const* d_in, const int* in_sizes, int n_in,
                              void* d_out, int out_size) {
    const float* feat   = (const float*)d_in[0];
    const int*   src    = (const int*)d_in[1];
    const int*   dst    = (const int*)d_in[2];
    const float* W      = (const float*)d_in[3];
    const float* attn_l = (const float*)d_in[4];
    const float* attn_r = (const float*)d_in[5];
    const float* bias   = (const float*)d_in[6];
    float* out = (float*)d_out;

    hist_kernel<<<(E_EDGES / 4 + 255) / 256, 256>>>(dst);
    scan_reduce_kernel<<<SCAN_BLOCKS, 1024>>>();
    scan_blocks_kernel<<<SCAN_BLOCKS, 1024>>>();
    gemm_kernel<<<(N_NODES + BR - 1) / BR, 256>>>(feat, W, attn_l, attn_r);
    scatter_kernel<<<(E_EDGES / 4 + 255) / 256, 256>>>(src, dst);
    agg_kernel<<<(N_NODES + 7) / 8, 256>>>(bias, out);
}